// round 17
// baseline (speedup 1.0000x reference)
#include <cuda_runtime.h>
#include <cuda_bf16.h>
#include <cstdint>

#define NN      20000
#define NE      60000
#define NODE_IN 8
#define EDGE_IN 4
#define HID     64
#define GD      64
#define NACT    20000
#define MLPH    128
#define BB      256
#define NCOL    4160              // 64*64 bilinear cols + 64 bias cols

// ---------------- scratch (device globals; no allocation) ----------------
__device__ float g_he1[NE * HID];
__device__ float g_he2[NE * HID];
__device__ float g_agg[NN * HID];
__device__ float g_deg[NN];
__device__ float g_h1[NN * HID];
__device__ float g_h2[NN * HID];
__device__ float g_colsum[HID];
__device__ float g_gw1[MLPH];
__device__ float g_z1[BB * MLPH];
__device__ __nv_bfloat16 g_Ub[(size_t)NN * NCOL];   // per-node transformed weights (166 MB, bf16)
__device__ float g_B1[NODE_IN * NCOL];              // layer-1 rearranged W2 (+bias cols), fp32
__device__ __nv_bfloat16 g_Bt[NCOL * HID];          // layer-2 B^T [col][k] bf16 (row.col B layout)
__device__ int   g_cnt[NN];
__device__ int   g_off[NN + 1];
__device__ int   g_cur[NN];
__device__ int   g_eidx[NE];

// ---------------- utility ----------------
// fused zero of agg, deg, cnt, z1
__global__ void k_zeroall(float* agg, float* deg, int* cnt, float* z1) {
    int i = blockIdx.x * 256 + threadIdx.x;
    if (i < NN * HID) agg[i] = 0.f;
    if (i < NN) { deg[i] = 0.f; cnt[i] = 0; }
    if (i < BB * MLPH) z1[i] = 0.f;
}

// fused degree (by dst) + count (by src)
__global__ void k_degcnt(const int* __restrict__ src, const int* __restrict__ dst,
                         float* __restrict__ deg, int* __restrict__ cnt) {
    int e = blockIdx.x * 256 + threadIdx.x;
    if (e < NE) {
        atomicAdd(&deg[dst[e]], 1.0f);
        atomicAdd(&cnt[src[e]], 1);
    }
}

__global__ __launch_bounds__(256) void k_scan(const int* __restrict__ cnt,
                                              int* __restrict__ off,
                                              int* __restrict__ cur) {
    __shared__ int sums[256];
    const int CH = (NN + 255) / 256;
    int t = threadIdx.x;
    int beg = t * CH;
    int s = 0;
    for (int i = 0; i < CH; i++) {
        int b = beg + i;
        if (b < NN) s += cnt[b];
    }
    sums[t] = s;
    __syncthreads();
    for (int stp = 1; stp < 256; stp <<= 1) {
        int v = (t >= stp) ? sums[t - stp] : 0;
        __syncthreads();
        sums[t] += v;
        __syncthreads();
    }
    int run = (t == 0) ? 0 : sums[t - 1];
    for (int i = 0; i < CH; i++) {
        int b = beg + i;
        if (b < NN) { off[b] = run; cur[b] = run; run += cnt[b]; }
    }
    if (t == 255) off[NN] = run;
}

__global__ void k_fill(const int* __restrict__ src, int* __restrict__ cur,
                       int* __restrict__ eidx) {
    int e = blockIdx.x * 256 + threadIdx.x;
    if (e < NE) {
        int p = atomicAdd(&cur[src[e]], 1);
        eidx[p] = e;
    }
}

// ---------------- edge MLPs (both layers in one launch; grid.y selects) ----------------
__global__ __launch_bounds__(256) void k_emlp2(const float* __restrict__ ea,
                                               const float* __restrict__ W1a,
                                               const float* __restrict__ b1a,
                                               float* __restrict__ ha,
                                               const float* __restrict__ W1b,
                                               const float* __restrict__ b1b,
                                               float* __restrict__ hb) {
    int idx = blockIdx.x * 256 + threadIdx.x;
    if (idx >= NE * HID) return;
    int e = idx >> 6, j = idx & 63;
    const float* W1 = blockIdx.y ? W1b : W1a;
    const float* b1 = blockIdx.y ? b1b : b1a;
    float* hout     = blockIdx.y ? hb  : ha;
    float s = b1[j];
#pragma unroll
    for (int c = 0; c < EDGE_IN; c++) s += ea[e * EDGE_IN + c] * W1[c * HID + j];
    hout[idx] = s > 0.f ? s : 0.f;
}

// ---------------- layer-1 rearranged weight B1[i, k*64+o] = W2[k, i*64+o]; bias cols ----------------
__global__ void k_buildB1(const float* __restrict__ W2, const float* __restrict__ b2,
                          float* __restrict__ B) {
    int idx = blockIdx.x * 256 + threadIdx.x;
    if (idx >= NODE_IN * NCOL) return;
    int i = idx / NCOL, col = idx - i * NCOL;
    float v;
    if (col < HID * HID) {
        int k = col >> 6, o = col & 63;
        v = W2[k * (NODE_IN * HID) + i * HID + o];
    } else {
        v = b2[i * HID + (col - HID * HID)];
    }
    B[idx] = v;
}

// ---------------- layer-2 B^T bf16: Bt[col, i] = B2[i, col] ----------------
__global__ void k_buildBt(const float* __restrict__ W2, const float* __restrict__ b2,
                          __nv_bfloat16* __restrict__ Bt) {
    int idx = blockIdx.x * 256 + threadIdx.x;   // col*64 + i
    if (idx >= NCOL * HID) return;
    int col = idx >> 6, i = idx & 63;
    float v;
    if (col < HID * HID) {
        int k = col >> 6, o = col & 63;
        v = W2[k * (HID * HID) + i * HID + o];
    } else {
        v = b2[i * HID + (col - HID * HID)];
    }
    Bt[idx] = __float2bfloat16(v);
}

// ---------------- Stage A, layer 1 (streaming, K=8): U = x @ B1 ----------------
// 32 rows x 64 cols per block, 256 threads, 1 row-slice of 8 cols per thread.
// Low regs -> high occupancy; HBM-write bound.
__global__ __launch_bounds__(256) void k_gemmU8(const float* __restrict__ A,
                                                const float* __restrict__ B,
                                                __nv_bfloat16* __restrict__ U) {
    __shared__ float Bsh[NODE_IN][64];   // 2 KB
    __shared__ float Ash[32][NODE_IN];   // 1 KB
    const int mbase = blockIdx.x * 32;
    const int nbase = blockIdx.y * 64;   // 65 * 64 == NCOL exactly
    const int t = threadIdx.x;

    // load B tile: 8 x 64 = 512 floats (2 per thread)
    {
        int idx = t;                      // covers 0..255
        int k = idx >> 6, c = idx & 63;
        Bsh[k][c] = B[k * NCOL + nbase + c];
        idx = t + 256;
        k = idx >> 6; c = idx & 63;
        Bsh[k][c] = B[k * NCOL + nbase + c];
    }
    // load A tile: 32 x 8 = 256 floats (1 per thread)
    {
        int m = t >> 3, k = t & 7;
        int gm = mbase + m; if (gm >= NN) gm = NN - 1;
        Ash[m][k] = A[gm * NODE_IN + k];
    }
    __syncthreads();

    const int m  = t >> 3;        // 0..31
    const int c0 = (t & 7) * 8;   // 0..56
    const int gm = mbase + m;
    if (gm >= NN) return;

    float acc[8];
#pragma unroll
    for (int c = 0; c < 8; c++) acc[c] = 0.f;
#pragma unroll
    for (int k = 0; k < NODE_IN; k++) {
        float av = Ash[m][k];
#pragma unroll
        for (int c = 0; c < 8; c++) acc[c] += av * Bsh[k][c0 + c];
    }

    __nv_bfloat162 p0 = __float22bfloat162_rn(make_float2(acc[0], acc[1]));
    __nv_bfloat162 p1 = __float22bfloat162_rn(make_float2(acc[2], acc[3]));
    __nv_bfloat162 p2 = __float22bfloat162_rn(make_float2(acc[4], acc[5]));
    __nv_bfloat162 p3 = __float22bfloat162_rn(make_float2(acc[6], acc[7]));
    uint4 v = make_uint4(*(uint32_t*)&p0, *(uint32_t*)&p1,
                         *(uint32_t*)&p2, *(uint32_t*)&p3);
    *(uint4*)(U + (size_t)gm * NCOL + nbase + c0) = v;
}

// ---------------- Stage A, layer 2 (mma.sync bf16 HMMA): U = h1 @ B2 ----------------
// 128x128 tile, 8 warps (4 M x 2 N), each warp 32x64 via m16n8k16 fragments, K=64.
#define SMSTR 72   // smem row stride in bf16 (144 B) - conflict-free fragment loads
__global__ __launch_bounds__(256) void k_gemmU_mma(const float* __restrict__ A,
                                                   const __nv_bfloat16* __restrict__ Bt,
                                                   __nv_bfloat16* __restrict__ U) {
    __shared__ __nv_bfloat16 As[128 * SMSTR];
    __shared__ __nv_bfloat16 Bs[128 * SMSTR];
    const int t = threadIdx.x;
    const int mbase = blockIdx.x * 128, nbase = blockIdx.y * 128;

    for (int p = t; p < 2048; p += 256) {
        int row = p >> 4, c4 = p & 15;
        int gm = mbase + row; if (gm >= NN) gm = NN - 1;
        float4 v = *(const float4*)(A + gm * HID + c4 * 4);
        __nv_bfloat162 lo = __float22bfloat162_rn(make_float2(v.x, v.y));
        __nv_bfloat162 hi = __float22bfloat162_rn(make_float2(v.z, v.w));
        uint32_t* dp = (uint32_t*)&As[row * SMSTR + c4 * 4];
        dp[0] = *(uint32_t*)&lo; dp[1] = *(uint32_t*)&hi;
    }
    for (int p = t; p < 2048; p += 256) {
        int n = p >> 4, k4 = p & 15;
        int gn = nbase + n;
        uint2 v = make_uint2(0, 0);
        if (gn < NCOL) v = *(const uint2*)(Bt + gn * HID + k4 * 4);
        *(uint2*)&Bs[n * SMSTR + k4 * 4] = v;
    }
    __syncthreads();

    const int wid = t >> 5, lane = t & 31;
    const int warp_m = wid & 3;
    const int warp_n = wid >> 2;
    const int grp = lane >> 2;
    const int qid = lane & 3;

    float acc[2][8][4];
#pragma unroll
    for (int mt = 0; mt < 2; mt++)
#pragma unroll
        for (int nt = 0; nt < 8; nt++)
#pragma unroll
            for (int q = 0; q < 4; q++) acc[mt][nt][q] = 0.f;

#pragma unroll
    for (int kc = 0; kc < 4; kc++) {
        const int k0 = kc * 16;
        uint32_t af[2][4];
#pragma unroll
        for (int mt = 0; mt < 2; mt++) {
            int r0 = warp_m * 32 + mt * 16 + grp;
            const __nv_bfloat16* ap = As + r0 * SMSTR + k0 + qid * 2;
            af[mt][0] = *(const uint32_t*)(ap);
            af[mt][1] = *(const uint32_t*)(ap + 8 * SMSTR);
            af[mt][2] = *(const uint32_t*)(ap + 8);
            af[mt][3] = *(const uint32_t*)(ap + 8 * SMSTR + 8);
        }
#pragma unroll
        for (int nt = 0; nt < 8; nt++) {
            int n = warp_n * 64 + nt * 8 + grp;
            const __nv_bfloat16* bp = Bs + n * SMSTR + k0 + qid * 2;
            uint32_t b0 = *(const uint32_t*)(bp);
            uint32_t b1 = *(const uint32_t*)(bp + 8);
#pragma unroll
            for (int mt = 0; mt < 2; mt++) {
                asm volatile(
                    "mma.sync.aligned.m16n8k16.row.col.f32.bf16.bf16.f32 "
                    "{%0,%1,%2,%3}, {%4,%5,%6,%7}, {%8,%9}, {%0,%1,%2,%3};"
                    : "+f"(acc[mt][nt][0]), "+f"(acc[mt][nt][1]),
                      "+f"(acc[mt][nt][2]), "+f"(acc[mt][nt][3])
                    : "r"(af[mt][0]), "r"(af[mt][1]), "r"(af[mt][2]), "r"(af[mt][3]),
                      "r"(b0), "r"(b1));
            }
        }
    }

#pragma unroll
    for (int mt = 0; mt < 2; mt++) {
        int r0 = mbase + warp_m * 32 + mt * 16 + grp;
#pragma unroll
        for (int nt = 0; nt < 8; nt++) {
            int gc = nbase + warp_n * 64 + nt * 8 + qid * 2;
            if (gc >= NCOL) continue;
            __nv_bfloat162 lo = __float22bfloat162_rn(make_float2(acc[mt][nt][0], acc[mt][nt][1]));
            __nv_bfloat162 hi = __float22bfloat162_rn(make_float2(acc[mt][nt][2], acc[mt][nt][3]));
            if (r0 < NN)
                *(uint32_t*)(U + (size_t)r0 * NCOL + gc) = *(uint32_t*)&lo;
            if (r0 + 8 < NN)
                *(uint32_t*)(U + (size_t)(r0 + 8) * NCOL + gc) = *(uint32_t*)&hi;
        }
    }
}

// ---------------- Stage B: per src-node, apply edge vectors & scatter ----------------
__global__ __launch_bounds__(128) void k_msgB(const float* __restrict__ he,
                                              const __nv_bfloat16* __restrict__ U,
                                              const int* __restrict__ off,
                                              const int* __restrict__ eidx,
                                              const int* __restrict__ dst,
                                              float* __restrict__ agg) {
    int n = blockIdx.x;
    int e0 = off[n], e1 = off[n + 1];
    if (e0 >= e1) return;

    __shared__ uint32_t Us[NCOL / 2];
    const int t = threadIdx.x;
    {
        const uint4* Up = (const uint4*)(U + (size_t)n * NCOL);
        uint4* Usp = (uint4*)Us;
        for (int i = t; i < NCOL / 8; i += 128) Usp[i] = Up[i];
    }
    __syncthreads();

    const int w = t >> 5, lane = t & 31;
    float2 ub;
    {
        uint32_t u = Us[2048 + lane];
        ub = __bfloat1622float2(*(__nv_bfloat162*)&u);
    }

    for (int j = e0 + 2 * w; j < e1; j += 8) {
        int eA = eidx[j];
        bool hasB = (j + 1 < e1);
        int eB = hasB ? eidx[j + 1] : eA;
        float hA0 = he[eA * 64 + lane], hA1 = he[eA * 64 + 32 + lane];
        float hB0 = he[eB * 64 + lane], hB1 = he[eB * 64 + 32 + lane];
        float aA0 = ub.x, aA1 = ub.y, aB0 = ub.x, aB1 = ub.y;
#pragma unroll
        for (int k = 0; k < 32; k++) {
            uint32_t u = Us[k * 32 + lane];
            float2 f = __bfloat1622float2(*(__nv_bfloat162*)&u);
            float hvA = __shfl_sync(0xffffffffu, hA0, k);
            float hvB = __shfl_sync(0xffffffffu, hB0, k);
            aA0 += hvA * f.x; aA1 += hvA * f.y;
            aB0 += hvB * f.x; aB1 += hvB * f.y;
        }
#pragma unroll
        for (int k = 0; k < 32; k++) {
            uint32_t u = Us[(32 + k) * 32 + lane];
            float2 f = __bfloat1622float2(*(__nv_bfloat162*)&u);
            float hvA = __shfl_sync(0xffffffffu, hA1, k);
            float hvB = __shfl_sync(0xffffffffu, hB1, k);
            aA0 += hvA * f.x; aA1 += hvA * f.y;
            aB0 += hvB * f.x; aB1 += hvB * f.y;
        }
        int dA = dst[eA];
        atomicAdd(&agg[dA * HID + 2 * lane], aA0);
        atomicAdd(&agg[dA * HID + 2 * lane + 1], aA1);
        if (hasB) {
            int dB = dst[eB];
            atomicAdd(&agg[dB * HID + 2 * lane], aB0);
            atomicAdd(&agg[dB * HID + 2 * lane + 1], aB1);
        }
    }
}

// ---------------- node update (also re-zeros agg for the next layer) ----------------
template <int NI>
__global__ __launch_bounds__(256) void k_node(float* __restrict__ agg,
                                              const float* __restrict__ deg,
                                              const float* __restrict__ xin,
                                              const float* __restrict__ root,
                                              const float* __restrict__ bias,
                                              float* __restrict__ hout) {
    int idx = blockIdx.x * 256 + threadIdx.x;
    if (idx >= NN * HID) return;
    int n = idx >> 6, o = idx & 63;
    float d = deg[n];
    if (d < 1.f) d = 1.f;
    float s = agg[idx] / d + bias[o];
    agg[idx] = 0.f;                 // reset for next use
#pragma unroll 8
    for (int i = 0; i < NI; i++) s += xin[n * NI + i] * root[i * HID + o];
    hout[idx] = s > 0.f ? s : 0.f;
}

// ---------------- global mean pool (column sums) ----------------
__global__ __launch_bounds__(256) void k_pool(const float* __restrict__ h2,
                                              float* __restrict__ colsum) {
    int o = blockIdx.x, t = threadIdx.x;
    float s = 0.f;
    for (int n = t; n < NN; n += 256) s += h2[n * HID + o];
    __shared__ float red[256];
    red[t] = s; __syncthreads();
    for (int st = 128; st > 0; st >>= 1) {
        if (t < st) red[t] += red[t + st];
        __syncthreads();
    }
    if (t == 0) colsum[o] = red[0];
}

// g = mean(h2) @ projW + projb;  gw1 = mb1 + g @ mW1[NACT:]
__global__ __launch_bounds__(128) void k_gcombine(const float* __restrict__ colsum,
                                                  const float* __restrict__ projW,
                                                  const float* __restrict__ projb,
                                                  const float* __restrict__ mW1,
                                                  const float* __restrict__ mb1,
                                                  float* __restrict__ gw1) {
    __shared__ float gsh[GD];
    int t = threadIdx.x;
    if (t < GD) {
        float s = projb[t];
        const float inv = 1.0f / NN;
        for (int o = 0; o < HID; o++) s += (colsum[o] * inv) * projW[o * GD + t];
        gsh[t] = s;
    }
    __syncthreads();
    float s = mb1[t];
    for (int d = 0; d < GD; d++) s += gsh[d] * mW1[(NACT + d) * MLPH + t];
    gw1[t] = s;
}

// ---------------- split-K GEMM: z1 += a[256,20000] @ mW1[:20000,128] ----------------
#define MLP_KCHUNK 500
__global__ __launch_bounds__(256) void k_mlp1(const float* __restrict__ a,
                                              const float* __restrict__ mW1,
                                              float* __restrict__ z1) {
    __shared__ float Ash[32][33];
    __shared__ float Bsh[32 * 128];
    const int rbase = blockIdx.x * 32;
    const int kbase = blockIdx.y * MLP_KCHUNK;
    const int t = threadIdx.x;
    const int row = t & 31;
    const int oc  = (t >> 5) * 16;

    float4 acc[4];
#pragma unroll
    for (int j = 0; j < 4; j++) acc[j] = make_float4(0, 0, 0, 0);

    for (int kk = 0; kk < MLP_KCHUNK; kk += 32) {
        __syncthreads();
        int kt = MLP_KCHUNK - kk; if (kt > 32) kt = 32;
#pragma unroll
        for (int it = 0; it < 4; it++) {
            int idx = t + it * 256;
            int r = idx >> 5, k = idx & 31;
            Ash[r][k] = (k < kt) ? a[(rbase + r) * NACT + kbase + kk + k] : 0.f;
        }
#pragma unroll
        for (int it = 0; it < 16; it++) {
            int idx = t + it * 256;
            int k = idx >> 7, o = idx & 127;
            Bsh[k * 128 + o] = (k < kt) ? mW1[(kbase + kk + k) * MLPH + o] : 0.f;
        }
        __syncthreads();
#pragma unroll 8
        for (int k = 0; k < 32; k++) {
            float av = Ash[row][k];
#pragma unroll
            for (int j = 0; j < 4; j++) {
                float4 b4 = *(const float4*)(Bsh + k * 128 + oc + j * 4);
                acc[j].x += av * b4.x; acc[j].y += av * b4.y;
                acc[j].z += av * b4.z; acc[j].w += av * b4.w;
            }
        }
    }
    float* p = z1 + (rbase + row) * MLPH + oc;
#pragma unroll
    for (int j = 0; j < 4; j++) {
        atomicAdd(p + j * 4 + 0, acc[j].x);
        atomicAdd(p + j * 4 + 1, acc[j].y);
        atomicAdd(p + j * 4 + 2, acc[j].z);
        atomicAdd(p + j * 4 + 3, acc[j].w);
    }
}

// ---------------- MLP tail ----------------
__global__ __launch_bounds__(128) void k_tail(const float* __restrict__ z1,
                                              const float* __restrict__ gw1,
                                              const float* __restrict__ mW2,
                                              const float* __restrict__ mb2,
                                              const float* __restrict__ mW3,
                                              const float* __restrict__ mb3,
                                              float* __restrict__ out) {
    int b = blockIdx.x, j = threadIdx.x;
    __shared__ float z1s[MLPH];
    __shared__ float red[MLPH];
    float v = z1[b * MLPH + j] + gw1[j];
    z1s[j] = v > 0.f ? v : 0.f;
    __syncthreads();
    float acc = mb2[j];
#pragma unroll 8
    for (int k = 0; k < MLPH; k++) acc += z1s[k] * mW2[k * MLPH + j];
    float z2 = acc > 0.f ? acc : 0.f;
    red[j] = z2 * mW3[j];
    __syncthreads();
    for (int st = 64; st > 0; st >>= 1) {
        if (j < st) red[j] += red[j + st];
        __syncthreads();
    }
    if (j == 0) out[b] = red[0] + mb3[0];
}

// ---------------- host ----------------
extern "C" void kernel_launch(void* const* d_in, const int* in_sizes, int n_in,
                              void* d_out, int out_size) {
    const float* x     = (const float*)d_in[0];
    const int*   ei    = (const int*)  d_in[1];
    const float* ea    = (const float*)d_in[2];
    const float* a     = (const float*)d_in[3];
    const float* e1W1  = (const float*)d_in[4];
    const float* e1b1  = (const float*)d_in[5];
    const float* e1W2  = (const float*)d_in[6];
    const float* e1b2  = (const float*)d_in[7];
    const float* root1 = (const float*)d_in[8];
    const float* bias1 = (const float*)d_in[9];
    const float* e2W1  = (const float*)d_in[10];
    const float* e2b1  = (const float*)d_in[11];
    const float* e2W2  = (const float*)d_in[12];
    const float* e2b2  = (const float*)d_in[13];
    const float* root2 = (const float*)d_in[14];
    const float* bias2 = (const float*)d_in[15];
    const float* projW = (const float*)d_in[16];
    const float* projb = (const float*)d_in[17];
    const float* mW1   = (const float*)d_in[18];
    const float* mb1   = (const float*)d_in[19];
    const float* mW2   = (const float*)d_in[20];
    const float* mb2   = (const float*)d_in[21];
    const float* mW3   = (const float*)d_in[22];
    const float* mb3   = (const float*)d_in[23];
    float* out = (float*)d_out;

    const int* srcp = ei;
    const int* dstp = ei + NE;

    float *p_he1, *p_he2, *p_agg, *p_deg, *p_h1, *p_h2, *p_col, *p_gw1, *p_z1, *p_B1;
    __nv_bfloat16 *p_Ub, *p_Bt;
    int *p_cnt, *p_off, *p_cur, *p_eidx;
    cudaGetSymbolAddress((void**)&p_he1, g_he1);
    cudaGetSymbolAddress((void**)&p_he2, g_he2);
    cudaGetSymbolAddress((void**)&p_agg, g_agg);
    cudaGetSymbolAddress((void**)&p_deg, g_deg);
    cudaGetSymbolAddress((void**)&p_h1,  g_h1);
    cudaGetSymbolAddress((void**)&p_h2,  g_h2);
    cudaGetSymbolAddress((void**)&p_col, g_colsum);
    cudaGetSymbolAddress((void**)&p_gw1, g_gw1);
    cudaGetSymbolAddress((void**)&p_z1,  g_z1);
    cudaGetSymbolAddress((void**)&p_Ub,  g_Ub);
    cudaGetSymbolAddress((void**)&p_B1,  g_B1);
    cudaGetSymbolAddress((void**)&p_Bt,  g_Bt);
    cudaGetSymbolAddress((void**)&p_cnt, g_cnt);
    cudaGetSymbolAddress((void**)&p_off, g_off);
    cudaGetSymbolAddress((void**)&p_cur, g_cur);
    cudaGetSymbolAddress((void**)&p_eidx, g_eidx);

    dim3 gA((NN + 127) / 128, (NCOL + 127) / 128);   // (157, 33) for mma
    dim3 gA8((NN + 31) / 32, NCOL / 64);             // (625, 65) streaming
    dim3 gE((NE * HID + 255) / 256, 2);

    // ---- setup (ordered so the heavy kernel lands in the ncu capture slot) ----
    k_buildB1<<<(NODE_IN * NCOL + 255) / 256, 256>>>(e1W2, e1b2, p_B1);      // 1
    k_zeroall<<<(NN * HID + 255) / 256, 256>>>(p_agg, p_deg, p_cnt, p_z1);   // 2
    k_buildBt<<<(NCOL * HID + 255) / 256, 256>>>(e2W2, e2b2, p_Bt);          // 3
    k_gemmU8<<<gA8, 256>>>(x, p_B1, p_Ub);                                   // 4 (heavy)
    k_emlp2<<<gE, 256>>>(ea, e1W1, e1b1, p_he1, e2W1, e2b1, p_he2);          // 5
    k_degcnt<<<(NE + 255) / 256, 256>>>(srcp, dstp, p_deg, p_cnt);           // 6
    k_scan<<<1, 256>>>(p_cnt, p_off, p_cur);                                 // 7
    k_fill<<<(NE + 255) / 256, 256>>>(srcp, p_cur, p_eidx);                  // 8

    // ---- layer 1 ----
    k_msgB<<<NN, 128>>>(p_he1, p_Ub, p_off, p_eidx, dstp, p_agg);
    k_node<NODE_IN><<<(NN * HID + 255) / 256, 256>>>(p_agg, p_deg, x, root1, bias1, p_h1);

    // ---- layer 2 (agg was re-zeroed by k_node) ----
    k_gemmU_mma<<<gA, 256>>>(p_h1, p_Bt, p_Ub);
    k_msgB<<<NN, 128>>>(p_he2, p_Ub, p_off, p_eidx, dstp, p_agg);
    k_node<HID><<<(NN * HID + 255) / 256, 256>>>(p_agg, p_deg, p_h1, root2, bias2, p_h2);

    // ---- pooling + fold g through mW1 ----
    k_pool<<<HID, 256>>>(p_h2, p_col);
    k_gcombine<<<1, 128>>>(p_col, projW, projb, mW1, mb1, p_gw1);

    // ---- MLP ----
    dim3 g1(BB / 32, NACT / MLP_KCHUNK);   // (8, 40)
    k_mlp1<<<g1, 256>>>(a, mW1, p_z1);
    k_tail<<<BB, 128>>>(p_z1, p_gw1, mW2, mb2, mW3, mb3, out);
}